// round 10
// baseline (speedup 1.0000x reference)
#include <cuda_runtime.h>
#include <cstdint>

// ---------------------------------------------------------------------------
// QuantumRNNCell fused persistent kernel, v10 (R8 pipeline @ 3 CTAs/SM):
//   out[b,h] = hx[b,h] + sum_j q[b,j] * fc_w[h,j] + fc_b[h]
// Block = 384 threads, 3 CTAs/SM (<=56 regs):
//   warps 0..3  : sim warps. Packed 2-rows-per-warp 6-qubit sim (16 lanes/row,
//                 4 complex amps/lane), analytic product-state encoding.
//                 Iter it: simulate tile t+stride into sq[(it+1)&1].
//   warps 4..11 : stream warps (256 thr, fixed column group, fc weights+bias
//                 in 28 registers). Iter it: cp.async tile t+stride into
//                 stage[(it+1)&1], then FMA+store tile t from stage[it&1].
// ONE __syncthreads per tile; next tile's loads always in flight during FMA.
// ---------------------------------------------------------------------------

#define NQ 6
#define NLAYERS 3
#define HDIM 1024
#define TR 8
#define STAGES 2
#define TILE_F4 (TR * 256)       // 2048 float4 per tile (32 KB)
#define NSIMW 4
#define NTHREADS 384

__device__ __forceinline__ void cp_async16(uint32_t dst, const void* src) {
    asm volatile("cp.async.cg.shared.global [%0], [%1], 16;"
                 :: "r"(dst), "l"(src));
}
__device__ __forceinline__ void cp_commit() {
    asm volatile("cp.async.commit_group;");
}
__device__ __forceinline__ void cp_wait1() {
    asm volatile("cp.async.wait_group 1;" ::: "memory");
}

// ---- packed (2-row) gate helpers (validated R4/R7/R8) ----------------------
// a[8] = {re,im} x hi2(0..3); hi2 bit1 = state bit5, hi2 bit0 = state bit4.
// State bits 3..0 = lane16 bits 3..0.
__device__ __forceinline__ void ry_pair(float a[8], int i0, int i1, float c, float s) {
    float re0 = a[2*i0], im0 = a[2*i0+1], re1 = a[2*i1], im1 = a[2*i1+1];
    a[2*i0]   = c*re0 - s*re1;
    a[2*i0+1] = c*im0 - s*im1;
    a[2*i1]   = s*re0 + c*re1;
    a[2*i1+1] = s*im0 + c*im1;
}
__device__ __forceinline__ void ry_shfl(float a[8], int m, float c, float s, unsigned lane) {
    float sg = (lane & (unsigned)m) ? s : -s;
#pragma unroll
    for (int k = 0; k < 4; k++) {
        float orr = __shfl_xor_sync(0xFFFFFFFFu, a[2*k],   m);
        float oii = __shfl_xor_sync(0xFFFFFFFFu, a[2*k+1], m);
        a[2*k]   = c*a[2*k]   + sg*orr;
        a[2*k+1] = c*a[2*k+1] + sg*oii;
    }
}
__device__ __forceinline__ void apply_ry(int w, float a[8], float c, float s, unsigned lane) {
    if (w == 0)      { ry_pair(a, 0, 2, c, s); ry_pair(a, 1, 3, c, s); }
    else if (w == 1) { ry_pair(a, 0, 1, c, s); ry_pair(a, 2, 3, c, s); }
    else             ry_shfl(a, 1 << (5 - w), c, s, lane);
}

__device__ __forceinline__ void apply_cnot_ring(int q, float a[8], unsigned lane) {
    if (q == 0) {
        float t;
        t = a[4]; a[4] = a[6]; a[6] = t;
        t = a[5]; a[5] = a[7]; a[7] = t;
    } else if (q == 1) {
#pragma unroll
        for (int k = 1; k < 4; k += 2) {
            a[2*k]   = __shfl_xor_sync(0xFFFFFFFFu, a[2*k],   8);
            a[2*k+1] = __shfl_xor_sync(0xFFFFFFFFu, a[2*k+1], 8);
        }
    } else if (q == 5) {
        if (lane & 1u) {
            float t;
            t = a[0]; a[0] = a[4]; a[4] = t;
            t = a[1]; a[1] = a[5]; a[5] = t;
            t = a[2]; a[2] = a[6]; a[6] = t;
            t = a[3]; a[3] = a[7]; a[7] = t;
        }
    } else {
        int cb = 1 << (5 - q);
        int tm = 1 << (4 - q);
        bool ctrl = (lane & (unsigned)cb) != 0;
#pragma unroll
        for (int k = 0; k < 4; k++) {
            float vr = __shfl_xor_sync(0xFFFFFFFFu, a[2*k],   tm);
            float vi = __shfl_xor_sync(0xFFFFFFFFu, a[2*k+1], tm);
            if (ctrl) { a[2*k] = vr; a[2*k+1] = vi; }
        }
    }
}

// ---- full sim for one row (half-warp) --------------------------------------
__device__ __forceinline__ void sim_rows(
    const float* __restrict__ x, const float* swc, const float* sws,
    float* sqdst, int trow, int b, unsigned lane, unsigned lane16) {
    float cx[NQ], sx[NQ];
#pragma unroll
    for (int j = 0; j < NQ; j++) {
        __sincosf(__ldg(&x[b * NQ + j]) * 0.5f, &sx[j], &cx[j]);
    }

    // per-wire v = RZ*RY*RX|0>
    float v0r[NQ], v0i[NQ], v1r[NQ], v1i[NQ];
#pragma unroll
    for (int iw = 0; iw < NQ; iw++) {
        int j1 = (iw + 1 > 5) ? iw - 5 : iw + 1;
        int j2 = (iw + 2 > 5) ? iw - 4 : iw + 2;
        float ar = cx[j1] * cx[iw];
        float ai = sx[j1] * sx[iw];
        float br = sx[j1] * cx[iw];
        float bi = -cx[j1] * sx[iw];
        float cz = cx[j2], sz = sx[j2];
        v0r[iw] = ar * cz + ai * sz;
        v0i[iw] = ai * cz - ar * sz;
        v1r[iw] = br * cz - bi * sz;
        v1i[iw] = bi * cz + br * sz;
    }

    // f = prod over wires 2..5; wire w bit = lane16 bit (5-w)
    float fr, fi;
    {
        bool bs = (lane16 & 8u) != 0;
        fr = bs ? v1r[2] : v0r[2];
        fi = bs ? v1i[2] : v0i[2];
    }
#pragma unroll
    for (int w2 = 3; w2 <= 5; w2++) {
        bool bs = (lane16 & (1u << (5 - w2))) != 0;
        float tr = bs ? v1r[w2] : v0r[w2];
        float ti = bs ? v1i[w2] : v0i[w2];
        float nr = fr * tr - fi * ti;
        float ni = fr * ti + fi * tr;
        fr = nr; fi = ni;
    }

    float a[8];
#pragma unroll
    for (int k = 0; k < 4; k++) {
        float u0r = (k & 2) ? v1r[0] : v0r[0];
        float u0i = (k & 2) ? v1i[0] : v0i[0];
        float u1r = (k & 1) ? v1r[1] : v0r[1];
        float u1i = (k & 1) ? v1i[1] : v0i[1];
        float gr = u0r * u1r - u0i * u1i;
        float gi = u0r * u1i + u0i * u1r;
        a[2*k]   = gr * fr - gi * fi;
        a[2*k+1] = gr * fi + gi * fr;
    }

#pragma unroll
    for (int l = 0; l < NLAYERS; l++) {
#pragma unroll
        for (int q = 0; q < NQ; q++)
            apply_ry(q, a, swc[l * NQ + q], sws[l * NQ + q], lane);
#pragma unroll
        for (int q = 0; q < NQ; q++) apply_cnot_ring(q, a, lane);
    }

    float p0 = a[0]*a[0] + a[1]*a[1];
    float p1 = a[2]*a[2] + a[3]*a[3];
    float p2 = a[4]*a[4] + a[5]*a[5];
    float p3 = a[6]*a[6] + a[7]*a[7];
    float ptot = p0 + p1 + p2 + p3;

    float e[NQ];
    e[0] = (p0 + p1) - (p2 + p3);
    e[1] = (p0 - p1) + (p2 - p3);
#pragma unroll
    for (int j = 2; j < NQ; j++) {
        float sg = (lane16 & (unsigned)(1 << (5 - j))) ? -1.0f : 1.0f;
        e[j] = sg * ptot;
    }
#pragma unroll
    for (int off = 8; off; off >>= 1) {
#pragma unroll
        for (int j = 0; j < NQ; j++)
            e[j] += __shfl_xor_sync(0xFFFFFFFFu, e[j], off);
    }
    if (lane16 == 0) {
#pragma unroll
        for (int j = 0; j < NQ; j++) sqdst[trow * 8 + j] = e[j];
        sqdst[trow * 8 + 6] = 0.0f;
        sqdst[trow * 8 + 7] = 0.0f;
    }
}

// ---- fused persistent kernel ------------------------------------------------
__global__ __launch_bounds__(NTHREADS, 3)
void fused_kernel(const float* __restrict__ x,
                  const float* __restrict__ hx,
                  const float* __restrict__ qw,    // (3,6)
                  const float* __restrict__ fc_w,  // (1024,6)
                  const float* __restrict__ fc_b,  // (1024,)
                  float* __restrict__ out,
                  int B, int ntiles) {
    extern __shared__ unsigned char smem_raw[];
    float4* sbuf = (float4*)smem_raw;                      // STAGES * TILE_F4
    float*  sq   = (float*)(sbuf + STAGES * TILE_F4);      // 2 * TR * 8
    float*  swc  = sq + 2 * TR * 8;                        // 18
    float*  sws  = swc + NLAYERS * NQ;                     // 18

    const int tid = threadIdx.x;
    const int warp = tid >> 5;
    const unsigned lane = tid & 31u;
    const unsigned lane16 = lane & 15u;
    const int half = (int)(lane >> 4);
    const int stride = gridDim.x;
    const int maxf4 = B * 256 - 1;
    const bool is_stream = (warp >= NSIMW);
    const int st = tid - NSIMW * 32;       // stream thread id 0..255

    // ---- stream threads: fc weights + bias into registers ----
    float4 w0, w1, w2, w3, w4, w5, bv;
    if (is_stream) {
        const int h0 = 4 * st;
        w0 = make_float4(__ldg(&fc_w[(h0+0)*NQ+0]), __ldg(&fc_w[(h0+1)*NQ+0]),
                         __ldg(&fc_w[(h0+2)*NQ+0]), __ldg(&fc_w[(h0+3)*NQ+0]));
        w1 = make_float4(__ldg(&fc_w[(h0+0)*NQ+1]), __ldg(&fc_w[(h0+1)*NQ+1]),
                         __ldg(&fc_w[(h0+2)*NQ+1]), __ldg(&fc_w[(h0+3)*NQ+1]));
        w2 = make_float4(__ldg(&fc_w[(h0+0)*NQ+2]), __ldg(&fc_w[(h0+1)*NQ+2]),
                         __ldg(&fc_w[(h0+2)*NQ+2]), __ldg(&fc_w[(h0+3)*NQ+2]));
        w3 = make_float4(__ldg(&fc_w[(h0+0)*NQ+3]), __ldg(&fc_w[(h0+1)*NQ+3]),
                         __ldg(&fc_w[(h0+2)*NQ+3]), __ldg(&fc_w[(h0+3)*NQ+3]));
        w4 = make_float4(__ldg(&fc_w[(h0+0)*NQ+4]), __ldg(&fc_w[(h0+1)*NQ+4]),
                         __ldg(&fc_w[(h0+2)*NQ+4]), __ldg(&fc_w[(h0+3)*NQ+4]));
        w5 = make_float4(__ldg(&fc_w[(h0+0)*NQ+5]), __ldg(&fc_w[(h0+1)*NQ+5]),
                         __ldg(&fc_w[(h0+2)*NQ+5]), __ldg(&fc_w[(h0+3)*NQ+5]));
        bv = make_float4(__ldg(&fc_b[h0]), __ldg(&fc_b[h0+1]),
                         __ldg(&fc_b[h0+2]), __ldg(&fc_b[h0+3]));
    }
    if (tid < NLAYERS * NQ) {
        float s, c;
        __sincosf(__ldg(&qw[tid]) * 0.5f, &s, &c);
        swc[tid] = c; sws[tid] = s;
    }
    __syncthreads();

    const int t0 = blockIdx.x;

    // ---- prologue: load+sim tile t0 ----
    if (is_stream) {
        if (t0 < ntiles) {
            uint32_t dstb = (uint32_t)__cvta_generic_to_shared(&sbuf[0]);
            const float4* srcb = (const float4*)hx;
            int base = t0 * TILE_F4;
#pragma unroll
            for (int k = 0; k < TR; k++) {
                int gi = min(base + k * 256 + st, maxf4);
                cp_async16(dstb + (uint32_t)(k * 256 + st) * 16u, srcb + gi);
            }
        }
        cp_commit();
    } else {
        const int trow = warp * 2 + half;
        sim_rows(x, swc, sws, sq, trow,
                 min(t0 * TR + trow, B - 1), lane, lane16);
    }
    __syncthreads();

    int it = 0;
    for (int t = t0; t < ntiles; t += stride, it++) {
        const int tn = t + stride;

        if (is_stream) {
            // ---- issue next tile's loads into the other stage ----
            if (tn < ntiles) {
                uint32_t dstb = (uint32_t)__cvta_generic_to_shared(
                    &sbuf[((it + 1) & 1) * TILE_F4]);
                const float4* srcb = (const float4*)hx;
                int base = tn * TILE_F4;
#pragma unroll
                for (int k = 0; k < TR; k++) {
                    int gi = min(base + k * 256 + st, maxf4);
                    cp_async16(dstb + (uint32_t)(k * 256 + st) * 16u, srcb + gi);
                }
            }
            cp_commit();
            cp_wait1();        // group for tile t complete; tn's stays pending

            // ---- FMA + store tile t ----
            const float4* buf = &sbuf[(it & 1) * TILE_F4];
            const float* sqr = &sq[(it & 1) * (TR * 8)];
            const int row0 = t * TR;
#pragma unroll
            for (int r = 0; r < TR; r++) {
                int b = row0 + r;
                if (b >= B) break;
                float4 qa = *(const float4*)&sqr[r * 8];
                float4 qb = *(const float4*)&sqr[r * 8 + 4];
                float4 v = buf[r * 256 + st];
                float4 acc = bv;
                acc.x += qa.x*w0.x; acc.y += qa.x*w0.y; acc.z += qa.x*w0.z; acc.w += qa.x*w0.w;
                acc.x += qa.y*w1.x; acc.y += qa.y*w1.y; acc.z += qa.y*w1.z; acc.w += qa.y*w1.w;
                acc.x += qa.z*w2.x; acc.y += qa.z*w2.y; acc.z += qa.z*w2.z; acc.w += qa.z*w2.w;
                acc.x += qa.w*w3.x; acc.y += qa.w*w3.y; acc.z += qa.w*w3.z; acc.w += qa.w*w3.w;
                acc.x += qb.x*w4.x; acc.y += qb.x*w4.y; acc.z += qb.x*w4.z; acc.w += qb.x*w4.w;
                acc.x += qb.y*w5.x; acc.y += qb.y*w5.y; acc.z += qb.y*w5.z; acc.w += qb.y*w5.w;
                v.x += acc.x; v.y += acc.y; v.z += acc.z; v.w += acc.w;
                __stcs((float4*)(out + (size_t)b * HDIM) + st, v);
            }
        } else {
            // ---- sim next tile into the other sq buffer ----
            if (tn < ntiles) {
                const int trow = warp * 2 + half;
                sim_rows(x, swc, sws, &sq[((it + 1) & 1) * (TR * 8)], trow,
                         min(tn * TR + trow, B - 1), lane, lane16);
            }
        }
        __syncthreads();       // sq/stage handoff for next iteration
    }
}

// ---- launch ----------------------------------------------------------------
extern "C" void kernel_launch(void* const* d_in, const int* in_sizes, int n_in,
                              void* d_out, int out_size) {
    const float* x    = (const float*)d_in[0];   // (B,6)
    const float* hx   = (const float*)d_in[1];   // (B,1024)
    const float* qw   = (const float*)d_in[2];   // (3,6)
    const float* fc_w = (const float*)d_in[3];   // (1024,6)
    const float* fc_b = (const float*)d_in[4];   // (1024,)
    float* out = (float*)d_out;

    int B = in_sizes[0] / NQ;
    int ntiles = (B + TR - 1) / TR;

    const int smem_bytes = STAGES * TILE_F4 * 16 + 2 * TR * 8 * 4
                         + 2 * NLAYERS * NQ * 4;

    cudaFuncSetAttribute(fused_kernel,
                         cudaFuncAttributeMaxDynamicSharedMemorySize,
                         smem_bytes);

    int grid = 148 * 3;
    if (grid > ntiles) grid = ntiles;
    fused_kernel<<<grid, NTHREADS, smem_bytes>>>(x, hx, qw, fc_w, fc_b, out,
                                                 B, ntiles);
}

// round 11
// speedup vs baseline: 1.6845x; 1.6845x over previous
#include <cuda_runtime.h>
#include <cstdint>

// ---------------------------------------------------------------------------
// QuantumRNNCell fused persistent kernel, v11 (R8 pipeline + f32x2 FMA):
//   out[b,h] = hx[b,h] + sum_j q[b,j] * fc_w[h,j] + fc_b[h]
// Block = 384 threads, 2 CTAs/SM (80 regs ok):
//   warps 0..3  : sim warps (packed 2-rows/warp 6-qubit sim, analytic
//                 product-state encoding). Write q DUPLICATED (q,q) pairs so
//                 stream warps can consume f32x2 broadcasts directly.
//   warps 4..11 : stream warps (256 thr, fixed 4-column group). fc weights
//                 held as 12 packed f32x2 registers; FMA phase uses
//                 fma.rn.f32x2 (FFMA2) -> ~19 issues/row instead of ~33.
// Double-buffered cp.async stage + sq; ONE __syncthreads per tile; next
// tile's loads always in flight during the FMA/store phase.
// ---------------------------------------------------------------------------

#define NQ 6
#define NLAYERS 3
#define HDIM 1024
#define TR 8
#define STAGES 2
#define TILE_F4 (TR * 256)       // 2048 float4 per tile (32 KB)
#define NSIMW 4
#define NTHREADS 384
#define SQROW 16                 // floats per sq row (12 used, padded)

__device__ __forceinline__ void cp_async16(uint32_t dst, const void* src) {
    asm volatile("cp.async.cg.shared.global [%0], [%1], 16;"
                 :: "r"(dst), "l"(src));
}
__device__ __forceinline__ void cp_commit() {
    asm volatile("cp.async.commit_group;");
}
__device__ __forceinline__ void cp_wait1() {
    asm volatile("cp.async.wait_group 1;" ::: "memory");
}

// ---- packed f32x2 helpers ---------------------------------------------------
__device__ __forceinline__ uint64_t pk2(float lo, float hi) {
    uint64_t r;
    asm("mov.b64 %0, {%1, %2};" : "=l"(r) : "f"(lo), "f"(hi));
    return r;
}
__device__ __forceinline__ uint64_t ffma2(uint64_t a, uint64_t b, uint64_t c) {
    uint64_t d;
    asm("fma.rn.f32x2 %0, %1, %2, %3;" : "=l"(d) : "l"(a), "l"(b), "l"(c));
    return d;
}
__device__ __forceinline__ uint64_t fadd2(uint64_t a, uint64_t b) {
    uint64_t d;
    asm("add.rn.f32x2 %0, %1, %2;" : "=l"(d) : "l"(a), "l"(b));
    return d;
}

// ---- packed (2-row) gate helpers (validated R4/R7/R8) ----------------------
// a[8] = {re,im} x hi2(0..3); hi2 bit1 = state bit5, hi2 bit0 = state bit4.
// State bits 3..0 = lane16 bits 3..0.
__device__ __forceinline__ void ry_pair(float a[8], int i0, int i1, float c, float s) {
    float re0 = a[2*i0], im0 = a[2*i0+1], re1 = a[2*i1], im1 = a[2*i1+1];
    a[2*i0]   = c*re0 - s*re1;
    a[2*i0+1] = c*im0 - s*im1;
    a[2*i1]   = s*re0 + c*re1;
    a[2*i1+1] = s*im0 + c*im1;
}
__device__ __forceinline__ void ry_shfl(float a[8], int m, float c, float s, unsigned lane) {
    float sg = (lane & (unsigned)m) ? s : -s;
#pragma unroll
    for (int k = 0; k < 4; k++) {
        float orr = __shfl_xor_sync(0xFFFFFFFFu, a[2*k],   m);
        float oii = __shfl_xor_sync(0xFFFFFFFFu, a[2*k+1], m);
        a[2*k]   = c*a[2*k]   + sg*orr;
        a[2*k+1] = c*a[2*k+1] + sg*oii;
    }
}
__device__ __forceinline__ void apply_ry(int w, float a[8], float c, float s, unsigned lane) {
    if (w == 0)      { ry_pair(a, 0, 2, c, s); ry_pair(a, 1, 3, c, s); }
    else if (w == 1) { ry_pair(a, 0, 1, c, s); ry_pair(a, 2, 3, c, s); }
    else             ry_shfl(a, 1 << (5 - w), c, s, lane);
}

__device__ __forceinline__ void apply_cnot_ring(int q, float a[8], unsigned lane) {
    if (q == 0) {
        float t;
        t = a[4]; a[4] = a[6]; a[6] = t;
        t = a[5]; a[5] = a[7]; a[7] = t;
    } else if (q == 1) {
#pragma unroll
        for (int k = 1; k < 4; k += 2) {
            a[2*k]   = __shfl_xor_sync(0xFFFFFFFFu, a[2*k],   8);
            a[2*k+1] = __shfl_xor_sync(0xFFFFFFFFu, a[2*k+1], 8);
        }
    } else if (q == 5) {
        if (lane & 1u) {
            float t;
            t = a[0]; a[0] = a[4]; a[4] = t;
            t = a[1]; a[1] = a[5]; a[5] = t;
            t = a[2]; a[2] = a[6]; a[6] = t;
            t = a[3]; a[3] = a[7]; a[7] = t;
        }
    } else {
        int cb = 1 << (5 - q);
        int tm = 1 << (4 - q);
        bool ctrl = (lane & (unsigned)cb) != 0;
#pragma unroll
        for (int k = 0; k < 4; k++) {
            float vr = __shfl_xor_sync(0xFFFFFFFFu, a[2*k],   tm);
            float vi = __shfl_xor_sync(0xFFFFFFFFu, a[2*k+1], tm);
            if (ctrl) { a[2*k] = vr; a[2*k+1] = vi; }
        }
    }
}

// ---- full sim for one row (half-warp); q written duplicated ----------------
__device__ __forceinline__ void sim_rows(
    const float* __restrict__ x, const float* swc, const float* sws,
    float* sqdst, int trow, int b, unsigned lane, unsigned lane16) {
    float cx[NQ], sx[NQ];
#pragma unroll
    for (int j = 0; j < NQ; j++) {
        __sincosf(__ldg(&x[b * NQ + j]) * 0.5f, &sx[j], &cx[j]);
    }

    // per-wire v = RZ*RY*RX|0>
    float v0r[NQ], v0i[NQ], v1r[NQ], v1i[NQ];
#pragma unroll
    for (int iw = 0; iw < NQ; iw++) {
        int j1 = (iw + 1 > 5) ? iw - 5 : iw + 1;
        int j2 = (iw + 2 > 5) ? iw - 4 : iw + 2;
        float ar = cx[j1] * cx[iw];
        float ai = sx[j1] * sx[iw];
        float br = sx[j1] * cx[iw];
        float bi = -cx[j1] * sx[iw];
        float cz = cx[j2], sz = sx[j2];
        v0r[iw] = ar * cz + ai * sz;
        v0i[iw] = ai * cz - ar * sz;
        v1r[iw] = br * cz - bi * sz;
        v1i[iw] = bi * cz + br * sz;
    }

    // f = prod over wires 2..5; wire w bit = lane16 bit (5-w)
    float fr, fi;
    {
        bool bs = (lane16 & 8u) != 0;
        fr = bs ? v1r[2] : v0r[2];
        fi = bs ? v1i[2] : v0i[2];
    }
#pragma unroll
    for (int w2 = 3; w2 <= 5; w2++) {
        bool bs = (lane16 & (1u << (5 - w2))) != 0;
        float tr = bs ? v1r[w2] : v0r[w2];
        float ti = bs ? v1i[w2] : v0i[w2];
        float nr = fr * tr - fi * ti;
        float ni = fr * ti + fi * tr;
        fr = nr; fi = ni;
    }

    float a[8];
#pragma unroll
    for (int k = 0; k < 4; k++) {
        float u0r = (k & 2) ? v1r[0] : v0r[0];
        float u0i = (k & 2) ? v1i[0] : v0i[0];
        float u1r = (k & 1) ? v1r[1] : v0r[1];
        float u1i = (k & 1) ? v1i[1] : v0i[1];
        float gr = u0r * u1r - u0i * u1i;
        float gi = u0r * u1i + u0i * u1r;
        a[2*k]   = gr * fr - gi * fi;
        a[2*k+1] = gr * fi + gi * fr;
    }

#pragma unroll
    for (int l = 0; l < NLAYERS; l++) {
#pragma unroll
        for (int q = 0; q < NQ; q++)
            apply_ry(q, a, swc[l * NQ + q], sws[l * NQ + q], lane);
#pragma unroll
        for (int q = 0; q < NQ; q++) apply_cnot_ring(q, a, lane);
    }

    float p0 = a[0]*a[0] + a[1]*a[1];
    float p1 = a[2]*a[2] + a[3]*a[3];
    float p2 = a[4]*a[4] + a[5]*a[5];
    float p3 = a[6]*a[6] + a[7]*a[7];
    float ptot = p0 + p1 + p2 + p3;

    float e[NQ];
    e[0] = (p0 + p1) - (p2 + p3);
    e[1] = (p0 - p1) + (p2 - p3);
#pragma unroll
    for (int j = 2; j < NQ; j++) {
        float sg = (lane16 & (unsigned)(1 << (5 - j))) ? -1.0f : 1.0f;
        e[j] = sg * ptot;
    }
#pragma unroll
    for (int off = 8; off; off >>= 1) {
#pragma unroll
        for (int j = 0; j < NQ; j++)
            e[j] += __shfl_xor_sync(0xFFFFFFFFu, e[j], off);
    }
    if (lane16 == 0) {
        // duplicated layout: [q0,q0,q1,q1,q2,q2, q3,q3,q4,q4,q5,q5, pad x4]
#pragma unroll
        for (int j = 0; j < NQ; j++) {
            sqdst[trow * SQROW + 2 * j]     = e[j];
            sqdst[trow * SQROW + 2 * j + 1] = e[j];
        }
    }
}

// ---- fused persistent kernel ------------------------------------------------
__global__ __launch_bounds__(NTHREADS, 2)
void fused_kernel(const float* __restrict__ x,
                  const float* __restrict__ hx,
                  const float* __restrict__ qw,    // (3,6)
                  const float* __restrict__ fc_w,  // (1024,6)
                  const float* __restrict__ fc_b,  // (1024,)
                  float* __restrict__ out,
                  int B, int ntiles) {
    extern __shared__ unsigned char smem_raw[];
    float4* sbuf = (float4*)smem_raw;                      // STAGES * TILE_F4
    float*  sq   = (float*)(sbuf + STAGES * TILE_F4);      // 2 * TR * SQROW
    float*  swc  = sq + 2 * TR * SQROW;                    // 18
    float*  sws  = swc + NLAYERS * NQ;                     // 18

    const int tid = threadIdx.x;
    const int warp = tid >> 5;
    const unsigned lane = tid & 31u;
    const unsigned lane16 = lane & 15u;
    const int half = (int)(lane >> 4);
    const int stride = gridDim.x;
    const int maxf4 = B * 256 - 1;
    const bool is_stream = (warp >= NSIMW);
    const int st = tid - NSIMW * 32;       // stream thread id 0..255

    // ---- stream threads: fc weights + bias as packed f32x2 registers ----
    uint64_t w0l=0,w0h=0,w1l=0,w1h=0,w2l=0,w2h=0,w3l=0,w3h=0,w4l=0,w4h=0,w5l=0,w5h=0;
    uint64_t bvl=0, bvh=0;
    if (is_stream) {
        const int h0 = 4 * st;
        w0l = pk2(__ldg(&fc_w[(h0+0)*NQ+0]), __ldg(&fc_w[(h0+1)*NQ+0]));
        w0h = pk2(__ldg(&fc_w[(h0+2)*NQ+0]), __ldg(&fc_w[(h0+3)*NQ+0]));
        w1l = pk2(__ldg(&fc_w[(h0+0)*NQ+1]), __ldg(&fc_w[(h0+1)*NQ+1]));
        w1h = pk2(__ldg(&fc_w[(h0+2)*NQ+1]), __ldg(&fc_w[(h0+3)*NQ+1]));
        w2l = pk2(__ldg(&fc_w[(h0+0)*NQ+2]), __ldg(&fc_w[(h0+1)*NQ+2]));
        w2h = pk2(__ldg(&fc_w[(h0+2)*NQ+2]), __ldg(&fc_w[(h0+3)*NQ+2]));
        w3l = pk2(__ldg(&fc_w[(h0+0)*NQ+3]), __ldg(&fc_w[(h0+1)*NQ+3]));
        w3h = pk2(__ldg(&fc_w[(h0+2)*NQ+3]), __ldg(&fc_w[(h0+3)*NQ+3]));
        w4l = pk2(__ldg(&fc_w[(h0+0)*NQ+4]), __ldg(&fc_w[(h0+1)*NQ+4]));
        w4h = pk2(__ldg(&fc_w[(h0+2)*NQ+4]), __ldg(&fc_w[(h0+3)*NQ+4]));
        w5l = pk2(__ldg(&fc_w[(h0+0)*NQ+5]), __ldg(&fc_w[(h0+1)*NQ+5]));
        w5h = pk2(__ldg(&fc_w[(h0+2)*NQ+5]), __ldg(&fc_w[(h0+3)*NQ+5]));
        bvl = pk2(__ldg(&fc_b[h0+0]), __ldg(&fc_b[h0+1]));
        bvh = pk2(__ldg(&fc_b[h0+2]), __ldg(&fc_b[h0+3]));
    }
    if (tid < NLAYERS * NQ) {
        float s, c;
        __sincosf(__ldg(&qw[tid]) * 0.5f, &s, &c);
        swc[tid] = c; sws[tid] = s;
    }
    __syncthreads();

    const int t0 = blockIdx.x;

    // ---- prologue: load+sim tile t0 ----
    if (is_stream) {
        if (t0 < ntiles) {
            uint32_t dstb = (uint32_t)__cvta_generic_to_shared(&sbuf[0]);
            const float4* srcb = (const float4*)hx;
            int base = t0 * TILE_F4;
#pragma unroll
            for (int k = 0; k < TR; k++) {
                int gi = min(base + k * 256 + st, maxf4);
                cp_async16(dstb + (uint32_t)(k * 256 + st) * 16u, srcb + gi);
            }
        }
        cp_commit();
    } else {
        const int trow = warp * 2 + half;
        sim_rows(x, swc, sws, sq, trow,
                 min(t0 * TR + trow, B - 1), lane, lane16);
    }
    __syncthreads();

    int it = 0;
    for (int t = t0; t < ntiles; t += stride, it++) {
        const int tn = t + stride;

        if (is_stream) {
            // ---- issue next tile's loads into the other stage ----
            if (tn < ntiles) {
                uint32_t dstb = (uint32_t)__cvta_generic_to_shared(
                    &sbuf[((it + 1) & 1) * TILE_F4]);
                const float4* srcb = (const float4*)hx;
                int base = tn * TILE_F4;
#pragma unroll
                for (int k = 0; k < TR; k++) {
                    int gi = min(base + k * 256 + st, maxf4);
                    cp_async16(dstb + (uint32_t)(k * 256 + st) * 16u, srcb + gi);
                }
            }
            cp_commit();
            cp_wait1();        // group for tile t complete; tn's stays pending

            // ---- FMA + store tile t (packed f32x2) ----
            const uint64_t* buf = (const uint64_t*)&sbuf[(it & 1) * TILE_F4];
            const float* sqr = &sq[(it & 1) * (TR * SQROW)];
            const int row0 = t * TR;
#pragma unroll
            for (int r = 0; r < TR; r++) {
                int b = row0 + r;
                if (b >= B) break;
                // q broadcasts, pre-duplicated: 3 x LDS.128
                ulonglong2 q01 = *(const ulonglong2*)&sqr[r * SQROW + 0];
                ulonglong2 q23 = *(const ulonglong2*)&sqr[r * SQROW + 4];
                ulonglong2 q45 = *(const ulonglong2*)&sqr[r * SQROW + 8];
                // hx value: 1 x LDS.128 (as two f32x2)
                ulonglong2 v = *(const ulonglong2*)&buf[(r * 256 + st) * 2];

                uint64_t lo = ffma2(q01.x, w0l, bvl);
                uint64_t hi = ffma2(q01.x, w0h, bvh);
                lo = ffma2(q01.y, w1l, lo);  hi = ffma2(q01.y, w1h, hi);
                lo = ffma2(q23.x, w2l, lo);  hi = ffma2(q23.x, w2h, hi);
                lo = ffma2(q23.y, w3l, lo);  hi = ffma2(q23.y, w3h, hi);
                lo = ffma2(q45.x, w4l, lo);  hi = ffma2(q45.x, w4h, hi);
                lo = ffma2(q45.y, w5l, lo);  hi = ffma2(q45.y, w5h, hi);
                lo = fadd2(lo, v.x);
                hi = fadd2(hi, v.y);

                float* dst = out + (size_t)b * HDIM + 4 * st;
                asm volatile("st.global.cs.v2.b64 [%0], {%1, %2};"
                             :: "l"(dst), "l"(lo), "l"(hi) : "memory");
            }
        } else {
            // ---- sim next tile into the other sq buffer ----
            if (tn < ntiles) {
                const int trow = warp * 2 + half;
                sim_rows(x, swc, sws, &sq[((it + 1) & 1) * (TR * SQROW)], trow,
                         min(tn * TR + trow, B - 1), lane, lane16);
            }
        }
        __syncthreads();       // sq/stage handoff for next iteration
    }
}

// ---- launch ----------------------------------------------------------------
extern "C" void kernel_launch(void* const* d_in, const int* in_sizes, int n_in,
                              void* d_out, int out_size) {
    const float* x    = (const float*)d_in[0];   // (B,6)
    const float* hx   = (const float*)d_in[1];   // (B,1024)
    const float* qw   = (const float*)d_in[2];   // (3,6)
    const float* fc_w = (const float*)d_in[3];   // (1024,6)
    const float* fc_b = (const float*)d_in[4];   // (1024,)
    float* out = (float*)d_out;

    int B = in_sizes[0] / NQ;
    int ntiles = (B + TR - 1) / TR;

    const int smem_bytes = STAGES * TILE_F4 * 16 + 2 * TR * SQROW * 4
                         + 2 * NLAYERS * NQ * 4;

    cudaFuncSetAttribute(fused_kernel,
                         cudaFuncAttributeMaxDynamicSharedMemorySize,
                         smem_bytes);

    int grid = 148 * 2;
    if (grid > ntiles) grid = ntiles;
    fused_kernel<<<grid, NTHREADS, smem_bytes>>>(x, hx, qw, fc_w, fc_b, out,
                                                 B, ntiles);
}

// round 12
// speedup vs baseline: 1.6913x; 1.0040x over previous
#include <cuda_runtime.h>
#include <cstdint>

// ---------------------------------------------------------------------------
// QuantumRNNCell fused persistent kernel, v12 (3-stage cp.async + f32x2 FMA):
//   out[b,h] = hx[b,h] + sum_j q[b,j] * fc_w[h,j] + fc_b[h]
// Block = 384 threads, 2 CTAs/SM:
//   warps 0..3  : sim warps (packed 2-rows/warp 6-qubit sim, analytic
//                 product-state encoding), q written duplicated for f32x2.
//   warps 4..11 : stream warps (256 thr, fixed 4-column group, weights as
//                 12 packed f32x2 regs; FFMA2 FMA phase).
// 3-stage cp.async pipeline, wait_group 2: during the FMA/store phase of
// tile t, the load groups for tiles t+1 AND t+2 are in flight (64KB/CTA).
// ONE __syncthreads per tile.
// ---------------------------------------------------------------------------

#define NQ 6
#define NLAYERS 3
#define HDIM 1024
#define TR 8
#define STAGES 3
#define TILE_F4 (TR * 256)       // 2048 float4 per tile (32 KB)
#define NSIMW 4
#define NTHREADS 384
#define SQROW 16                 // floats per sq row (12 used, padded)

__device__ __forceinline__ void cp_async16(uint32_t dst, const void* src) {
    asm volatile("cp.async.cg.shared.global [%0], [%1], 16;"
                 :: "r"(dst), "l"(src));
}
__device__ __forceinline__ void cp_commit() {
    asm volatile("cp.async.commit_group;");
}
__device__ __forceinline__ void cp_wait2() {
    asm volatile("cp.async.wait_group 2;" ::: "memory");
}

// ---- packed f32x2 helpers ---------------------------------------------------
__device__ __forceinline__ uint64_t pk2(float lo, float hi) {
    uint64_t r;
    asm("mov.b64 %0, {%1, %2};" : "=l"(r) : "f"(lo), "f"(hi));
    return r;
}
__device__ __forceinline__ uint64_t ffma2(uint64_t a, uint64_t b, uint64_t c) {
    uint64_t d;
    asm("fma.rn.f32x2 %0, %1, %2, %3;" : "=l"(d) : "l"(a), "l"(b), "l"(c));
    return d;
}
__device__ __forceinline__ uint64_t fadd2(uint64_t a, uint64_t b) {
    uint64_t d;
    asm("add.rn.f32x2 %0, %1, %2;" : "=l"(d) : "l"(a), "l"(b));
    return d;
}

// ---- packed (2-row) gate helpers (validated R4/R7/R8) ----------------------
// a[8] = {re,im} x hi2(0..3); hi2 bit1 = state bit5, hi2 bit0 = state bit4.
// State bits 3..0 = lane16 bits 3..0.
__device__ __forceinline__ void ry_pair(float a[8], int i0, int i1, float c, float s) {
    float re0 = a[2*i0], im0 = a[2*i0+1], re1 = a[2*i1], im1 = a[2*i1+1];
    a[2*i0]   = c*re0 - s*re1;
    a[2*i0+1] = c*im0 - s*im1;
    a[2*i1]   = s*re0 + c*re1;
    a[2*i1+1] = s*im0 + c*im1;
}
__device__ __forceinline__ void ry_shfl(float a[8], int m, float c, float s, unsigned lane) {
    float sg = (lane & (unsigned)m) ? s : -s;
#pragma unroll
    for (int k = 0; k < 4; k++) {
        float orr = __shfl_xor_sync(0xFFFFFFFFu, a[2*k],   m);
        float oii = __shfl_xor_sync(0xFFFFFFFFu, a[2*k+1], m);
        a[2*k]   = c*a[2*k]   + sg*orr;
        a[2*k+1] = c*a[2*k+1] + sg*oii;
    }
}
__device__ __forceinline__ void apply_ry(int w, float a[8], float c, float s, unsigned lane) {
    if (w == 0)      { ry_pair(a, 0, 2, c, s); ry_pair(a, 1, 3, c, s); }
    else if (w == 1) { ry_pair(a, 0, 1, c, s); ry_pair(a, 2, 3, c, s); }
    else             ry_shfl(a, 1 << (5 - w), c, s, lane);
}

__device__ __forceinline__ void apply_cnot_ring(int q, float a[8], unsigned lane) {
    if (q == 0) {
        float t;
        t = a[4]; a[4] = a[6]; a[6] = t;
        t = a[5]; a[5] = a[7]; a[7] = t;
    } else if (q == 1) {
#pragma unroll
        for (int k = 1; k < 4; k += 2) {
            a[2*k]   = __shfl_xor_sync(0xFFFFFFFFu, a[2*k],   8);
            a[2*k+1] = __shfl_xor_sync(0xFFFFFFFFu, a[2*k+1], 8);
        }
    } else if (q == 5) {
        if (lane & 1u) {
            float t;
            t = a[0]; a[0] = a[4]; a[4] = t;
            t = a[1]; a[1] = a[5]; a[5] = t;
            t = a[2]; a[2] = a[6]; a[6] = t;
            t = a[3]; a[3] = a[7]; a[7] = t;
        }
    } else {
        int cb = 1 << (5 - q);
        int tm = 1 << (4 - q);
        bool ctrl = (lane & (unsigned)cb) != 0;
#pragma unroll
        for (int k = 0; k < 4; k++) {
            float vr = __shfl_xor_sync(0xFFFFFFFFu, a[2*k],   tm);
            float vi = __shfl_xor_sync(0xFFFFFFFFu, a[2*k+1], tm);
            if (ctrl) { a[2*k] = vr; a[2*k+1] = vi; }
        }
    }
}

// ---- full sim for one row (half-warp); q written duplicated ----------------
__device__ __forceinline__ void sim_rows(
    const float* __restrict__ x, const float* swc, const float* sws,
    float* sqdst, int trow, int b, unsigned lane, unsigned lane16) {
    float cx[NQ], sx[NQ];
#pragma unroll
    for (int j = 0; j < NQ; j++) {
        __sincosf(__ldg(&x[b * NQ + j]) * 0.5f, &sx[j], &cx[j]);
    }

    // per-wire v = RZ*RY*RX|0>
    float v0r[NQ], v0i[NQ], v1r[NQ], v1i[NQ];
#pragma unroll
    for (int iw = 0; iw < NQ; iw++) {
        int j1 = (iw + 1 > 5) ? iw - 5 : iw + 1;
        int j2 = (iw + 2 > 5) ? iw - 4 : iw + 2;
        float ar = cx[j1] * cx[iw];
        float ai = sx[j1] * sx[iw];
        float br = sx[j1] * cx[iw];
        float bi = -cx[j1] * sx[iw];
        float cz = cx[j2], sz = sx[j2];
        v0r[iw] = ar * cz + ai * sz;
        v0i[iw] = ai * cz - ar * sz;
        v1r[iw] = br * cz - bi * sz;
        v1i[iw] = bi * cz + br * sz;
    }

    // f = prod over wires 2..5; wire w bit = lane16 bit (5-w)
    float fr, fi;
    {
        bool bs = (lane16 & 8u) != 0;
        fr = bs ? v1r[2] : v0r[2];
        fi = bs ? v1i[2] : v0i[2];
    }
#pragma unroll
    for (int w2 = 3; w2 <= 5; w2++) {
        bool bs = (lane16 & (1u << (5 - w2))) != 0;
        float tr = bs ? v1r[w2] : v0r[w2];
        float ti = bs ? v1i[w2] : v0i[w2];
        float nr = fr * tr - fi * ti;
        float ni = fr * ti + fi * tr;
        fr = nr; fi = ni;
    }

    float a[8];
#pragma unroll
    for (int k = 0; k < 4; k++) {
        float u0r = (k & 2) ? v1r[0] : v0r[0];
        float u0i = (k & 2) ? v1i[0] : v0i[0];
        float u1r = (k & 1) ? v1r[1] : v0r[1];
        float u1i = (k & 1) ? v1i[1] : v0i[1];
        float gr = u0r * u1r - u0i * u1i;
        float gi = u0r * u1i + u0i * u1r;
        a[2*k]   = gr * fr - gi * fi;
        a[2*k+1] = gr * fi + gi * fr;
    }

#pragma unroll
    for (int l = 0; l < NLAYERS; l++) {
#pragma unroll
        for (int q = 0; q < NQ; q++)
            apply_ry(q, a, swc[l * NQ + q], sws[l * NQ + q], lane);
#pragma unroll
        for (int q = 0; q < NQ; q++) apply_cnot_ring(q, a, lane);
    }

    float p0 = a[0]*a[0] + a[1]*a[1];
    float p1 = a[2]*a[2] + a[3]*a[3];
    float p2 = a[4]*a[4] + a[5]*a[5];
    float p3 = a[6]*a[6] + a[7]*a[7];
    float ptot = p0 + p1 + p2 + p3;

    float e[NQ];
    e[0] = (p0 + p1) - (p2 + p3);
    e[1] = (p0 - p1) + (p2 - p3);
#pragma unroll
    for (int j = 2; j < NQ; j++) {
        float sg = (lane16 & (unsigned)(1 << (5 - j))) ? -1.0f : 1.0f;
        e[j] = sg * ptot;
    }
#pragma unroll
    for (int off = 8; off; off >>= 1) {
#pragma unroll
        for (int j = 0; j < NQ; j++)
            e[j] += __shfl_xor_sync(0xFFFFFFFFu, e[j], off);
    }
    if (lane16 == 0) {
        // duplicated layout: [q0,q0,q1,q1,q2,q2, q3,q3,q4,q4,q5,q5, pad x4]
#pragma unroll
        for (int j = 0; j < NQ; j++) {
            sqdst[trow * SQROW + 2 * j]     = e[j];
            sqdst[trow * SQROW + 2 * j + 1] = e[j];
        }
    }
}

// ---- fused persistent kernel ------------------------------------------------
__global__ __launch_bounds__(NTHREADS, 2)
void fused_kernel(const float* __restrict__ x,
                  const float* __restrict__ hx,
                  const float* __restrict__ qw,    // (3,6)
                  const float* __restrict__ fc_w,  // (1024,6)
                  const float* __restrict__ fc_b,  // (1024,)
                  float* __restrict__ out,
                  int B, int ntiles) {
    extern __shared__ unsigned char smem_raw[];
    float4* sbuf = (float4*)smem_raw;                      // STAGES * TILE_F4
    float*  sq   = (float*)(sbuf + STAGES * TILE_F4);      // 2 * TR * SQROW
    float*  swc  = sq + 2 * TR * SQROW;                    // 18
    float*  sws  = swc + NLAYERS * NQ;                     // 18

    const int tid = threadIdx.x;
    const int warp = tid >> 5;
    const unsigned lane = tid & 31u;
    const unsigned lane16 = lane & 15u;
    const int half = (int)(lane >> 4);
    const int stride = gridDim.x;
    const int maxf4 = B * 256 - 1;
    const bool is_stream = (warp >= NSIMW);
    const int st = tid - NSIMW * 32;       // stream thread id 0..255

    // ---- stream threads: fc weights + bias as packed f32x2 registers ----
    uint64_t w0l=0,w0h=0,w1l=0,w1h=0,w2l=0,w2h=0,w3l=0,w3h=0,w4l=0,w4h=0,w5l=0,w5h=0;
    uint64_t bvl=0, bvh=0;
    if (is_stream) {
        const int h0 = 4 * st;
        w0l = pk2(__ldg(&fc_w[(h0+0)*NQ+0]), __ldg(&fc_w[(h0+1)*NQ+0]));
        w0h = pk2(__ldg(&fc_w[(h0+2)*NQ+0]), __ldg(&fc_w[(h0+3)*NQ+0]));
        w1l = pk2(__ldg(&fc_w[(h0+0)*NQ+1]), __ldg(&fc_w[(h0+1)*NQ+1]));
        w1h = pk2(__ldg(&fc_w[(h0+2)*NQ+1]), __ldg(&fc_w[(h0+3)*NQ+1]));
        w2l = pk2(__ldg(&fc_w[(h0+0)*NQ+2]), __ldg(&fc_w[(h0+1)*NQ+2]));
        w2h = pk2(__ldg(&fc_w[(h0+2)*NQ+2]), __ldg(&fc_w[(h0+3)*NQ+2]));
        w3l = pk2(__ldg(&fc_w[(h0+0)*NQ+3]), __ldg(&fc_w[(h0+1)*NQ+3]));
        w3h = pk2(__ldg(&fc_w[(h0+2)*NQ+3]), __ldg(&fc_w[(h0+3)*NQ+3]));
        w4l = pk2(__ldg(&fc_w[(h0+0)*NQ+4]), __ldg(&fc_w[(h0+1)*NQ+4]));
        w4h = pk2(__ldg(&fc_w[(h0+2)*NQ+4]), __ldg(&fc_w[(h0+3)*NQ+4]));
        w5l = pk2(__ldg(&fc_w[(h0+0)*NQ+5]), __ldg(&fc_w[(h0+1)*NQ+5]));
        w5h = pk2(__ldg(&fc_w[(h0+2)*NQ+5]), __ldg(&fc_w[(h0+3)*NQ+5]));
        bvl = pk2(__ldg(&fc_b[h0+0]), __ldg(&fc_b[h0+1]));
        bvh = pk2(__ldg(&fc_b[h0+2]), __ldg(&fc_b[h0+3]));
    }
    if (tid < NLAYERS * NQ) {
        float s, c;
        __sincosf(__ldg(&qw[tid]) * 0.5f, &s, &c);
        swc[tid] = c; sws[tid] = s;
    }
    __syncthreads();

    const int t0 = blockIdx.x;

    // ---- prologue: issue tiles t0 (stage 0) and t0+stride (stage 1);
    //      sim tile t0 -> sq[0] ----
    if (is_stream) {
#pragma unroll
        for (int p = 0; p < 2; p++) {
            int t = t0 + p * stride;
            if (t < ntiles) {
                uint32_t dstb = (uint32_t)__cvta_generic_to_shared(
                    &sbuf[p * TILE_F4]);
                const float4* srcb = (const float4*)hx;
                int base = t * TILE_F4;
#pragma unroll
                for (int k = 0; k < TR; k++) {
                    int gi = min(base + k * 256 + st, maxf4);
                    cp_async16(dstb + (uint32_t)(k * 256 + st) * 16u, srcb + gi);
                }
            }
            cp_commit();
        }
    } else {
        const int trow = warp * 2 + half;
        sim_rows(x, swc, sws, sq, trow,
                 min(t0 * TR + trow, B - 1), lane, lane16);
    }
    __syncthreads();

    int it = 0;
    int s_cons = 0;                 // stage holding tile t
    int s_issue = 2;                // stage to fill with tile t+2*stride
    for (int t = t0; t < ntiles; t += stride, it++) {
        const int tn = t + stride;

        if (is_stream) {
            // ---- issue tile t+2*stride into stage s_issue ----
            {
                int t2 = t + 2 * stride;
                if (t2 < ntiles) {
                    uint32_t dstb = (uint32_t)__cvta_generic_to_shared(
                        &sbuf[s_issue * TILE_F4]);
                    const float4* srcb = (const float4*)hx;
                    int base = t2 * TILE_F4;
#pragma unroll
                    for (int k = 0; k < TR; k++) {
                        int gi = min(base + k * 256 + st, maxf4);
                        cp_async16(dstb + (uint32_t)(k * 256 + st) * 16u, srcb + gi);
                    }
                }
                cp_commit();
            }
            cp_wait2();    // tile t's group complete; t+1, t+2 stay in flight

            // ---- FMA + store tile t (packed f32x2) ----
            const uint64_t* buf = (const uint64_t*)&sbuf[s_cons * TILE_F4];
            const float* sqr = &sq[(it & 1) * (TR * SQROW)];
            const int row0 = t * TR;
#pragma unroll
            for (int r = 0; r < TR; r++) {
                int b = row0 + r;
                if (b >= B) break;
                ulonglong2 q01 = *(const ulonglong2*)&sqr[r * SQROW + 0];
                ulonglong2 q23 = *(const ulonglong2*)&sqr[r * SQROW + 4];
                ulonglong2 q45 = *(const ulonglong2*)&sqr[r * SQROW + 8];
                ulonglong2 v = *(const ulonglong2*)&buf[(r * 256 + st) * 2];

                uint64_t lo = ffma2(q01.x, w0l, bvl);
                uint64_t hi = ffma2(q01.x, w0h, bvh);
                lo = ffma2(q01.y, w1l, lo);  hi = ffma2(q01.y, w1h, hi);
                lo = ffma2(q23.x, w2l, lo);  hi = ffma2(q23.x, w2h, hi);
                lo = ffma2(q23.y, w3l, lo);  hi = ffma2(q23.y, w3h, hi);
                lo = ffma2(q45.x, w4l, lo);  hi = ffma2(q45.x, w4h, hi);
                lo = ffma2(q45.y, w5l, lo);  hi = ffma2(q45.y, w5h, hi);
                lo = fadd2(lo, v.x);
                hi = fadd2(hi, v.y);

                float* dst = out + (size_t)b * HDIM + 4 * st;
                asm volatile("st.global.cs.v2.b64 [%0], {%1, %2};"
                             :: "l"(dst), "l"(lo), "l"(hi) : "memory");
            }
        } else {
            // ---- sim tile t+stride into the other sq buffer ----
            if (tn < ntiles) {
                const int trow = warp * 2 + half;
                sim_rows(x, swc, sws, &sq[((it + 1) & 1) * (TR * SQROW)], trow,
                         min(tn * TR + trow, B - 1), lane, lane16);
            }
        }
        // advance stage counters (mod 3)
        s_cons = (s_cons == 2) ? 0 : s_cons + 1;
        s_issue = (s_issue == 2) ? 0 : s_issue + 1;
        __syncthreads();    // orders stage/sq reads before next iter's fills
    }
}

// ---- launch ----------------------------------------------------------------
extern "C" void kernel_launch(void* const* d_in, const int* in_sizes, int n_in,
                              void* d_out, int out_size) {
    const float* x    = (const float*)d_in[0];   // (B,6)
    const float* hx   = (const float*)d_in[1];   // (B,1024)
    const float* qw   = (const float*)d_in[2];   // (3,6)
    const float* fc_w = (const float*)d_in[3];   // (1024,6)
    const float* fc_b = (const float*)d_in[4];   // (1024,)
    float* out = (float*)d_out;

    int B = in_sizes[0] / NQ;
    int ntiles = (B + TR - 1) / TR;

    const int smem_bytes = STAGES * TILE_F4 * 16 + 2 * TR * SQROW * 4
                         + 2 * NLAYERS * NQ * 4;

    cudaFuncSetAttribute(fused_kernel,
                         cudaFuncAttributeMaxDynamicSharedMemorySize,
                         smem_bytes);

    int grid = 148 * 2;
    if (grid > ntiles) grid = ntiles;
    fused_kernel<<<grid, NTHREADS, smem_bytes>>>(x, hx, qw, fc_w, fc_b, out,
                                                 B, ntiles);
}